// round 10
// baseline (speedup 1.0000x reference)
#include <cuda_runtime.h>
#include <cuda_fp16.h>
#include <math.h>
#include <stdint.h>

// ---------------------------------------------------------------------------
// SwinV2 block: B=32, H=W=48, C=384, NH=12, WS=12, N=144, SHIFT=6
// GEMMs: fp16 mma.m16n8k16 (fp32 accum), 4-stage cp.async, ldmatrix frags.
// ---------------------------------------------------------------------------
namespace {
constexpr int kH = 48;
constexpr int kW = 48;
constexpr int kC = 384;
constexpr int kNH = 12;
constexpr int kHD = 32;
constexpr int kWS = 12;
constexpr int kN = 144;
constexpr int kSHIFT = 6;
constexpr int kM = 73728;        // 512 windows * 144 tokens
constexpr long kSLOT = 28311552; // kM * kC elements

constexpr int ST2 = 20;          // smem row stride in 32-bit words (40 halves)
constexpr int BUFW = 128 * ST2;  // words per operand buffer (2560)
constexpr int STAGEW = 2 * BUFW; // A | B per stage (5120 words)
constexpr int NSTAGE = 4;
constexpr int SMEM_DYN = NSTAGE * STAGEW * 4;  // 81920 B

// fp16 weight offsets (halves), [n][k] layout
constexpr long OQKV = 0;        // 1152 x 384
constexpr long OPROJ = 442368;  // 384 x 384
constexpr long OFC1 = 589824;   // 1536 x 384
constexpr long OFC2 = 1179648;  // 384 x 1536
}

// scratch slots (28311552 f32 each):
// s0 q | s1 k -> x1 f32 | s2 v -> h_h(spans s2,s3) | s3 attn_h
// s4 x_h -> x1_h | s5 proj_f | s7 y_f
__device__ float g_scratch[8 * 28311552ULL];
__device__ float g_btab[529 * 12];
__device__ float g_bias2[16 * 12 * 144 * 144];
__device__ __align__(16) __half g_whi[1769472];

__device__ __forceinline__ int win_src_row(int m) {
    int wi = m / kN, t = m - wi * kN;
    int b  = wi >> 4;
    int wh = (wi >> 2) & 3;
    int ww = wi & 3;
    int th = t / kWS, tw = t - th * kWS;
    int sh = wh * kWS + th + kSHIFT; if (sh >= kH) sh -= kH;
    int sw = ww * kWS + tw + kSHIFT; if (sw >= kW) sw -= kW;
    return (b * kH + sh) * kW + sw;
}

__device__ __forceinline__ uint32_t smem_u32(const void* p) {
    uint32_t a;
    asm("{ .reg .u64 t; cvta.to.shared.u64 t, %1; cvt.u32.u64 %0, t; }" : "=r"(a) : "l"(p));
    return a;
}
__device__ __forceinline__ void mma16(float* c, const uint32_t* a, const uint32_t* b) {
    asm volatile("mma.sync.aligned.m16n8k16.row.col.f32.f16.f16.f32 "
        "{%0,%1,%2,%3},{%4,%5,%6,%7},{%8,%9},{%0,%1,%2,%3};"
        : "+f"(c[0]), "+f"(c[1]), "+f"(c[2]), "+f"(c[3])
        : "r"(a[0]), "r"(a[1]), "r"(a[2]), "r"(a[3]), "r"(b[0]), "r"(b[1]));
}
__device__ __forceinline__ void ldsm_x4(uint32_t* r, uint32_t addr) {
    asm volatile("ldmatrix.sync.aligned.m8n8.x4.shared.b16 {%0,%1,%2,%3}, [%4];"
        : "=r"(r[0]), "=r"(r[1]), "=r"(r[2]), "=r"(r[3]) : "r"(addr));
}
__device__ __forceinline__ void cpa16(uint32_t dst, const void* src) {
    asm volatile("cp.async.ca.shared.global [%0], [%1], 16;" :: "r"(dst), "l"(src));
}
__device__ __forceinline__ void cpa_commit() {
    asm volatile("cp.async.commit_group;" ::: "memory");
}
template <int Nw>
__device__ __forceinline__ void cpa_wait() {
    asm volatile("cp.async.wait_group %0;" :: "n"(Nw) : "memory");
}

// ---------------------------------------------------------------------------
// K0a: weight transpose to fp16.  W[K][N] -> hi[n][k]
// ---------------------------------------------------------------------------
__global__ void wsplit_kernel(const float* __restrict__ W,
                              __half* __restrict__ hi, int K, int N) {
    long idx = (long)blockIdx.x * 256 + threadIdx.x;
    if (idx >= (long)K * N) return;
    int n = (int)(idx / K), k = (int)(idx % K);
    hi[idx] = __float2half_rn(W[(long)k * N + n]);
}

// K0b: activation convert
__global__ void xsplit_kernel(const float* __restrict__ X,
                              __half* __restrict__ hi, long n) {
    long i = (long)blockIdx.x * 256 + threadIdx.x;
    if (i < n) hi[i] = __float2half_rn(X[i]);
}

// ---------------------------------------------------------------------------
// K1: CPB MLP -> 16*sigmoid table; K1b: expand + fold mask
// ---------------------------------------------------------------------------
__global__ void cpb_kernel(const float* __restrict__ table,
                           const float* __restrict__ w1,
                           const float* __restrict__ b1,
                           const float* __restrict__ w2) {
    __shared__ float hid[512];
    int e = blockIdx.x;
    int tid = threadIdx.x;
    float t0 = table[e * 2 + 0], t1 = table[e * 2 + 1];
    hid[tid] = fmaxf(0.f, fmaf(t0, w1[tid], fmaf(t1, w1[512 + tid], b1[tid])));
    __syncthreads();
    if (tid < 12) {
        float s = 0.f;
        #pragma unroll 8
        for (int i = 0; i < 512; i++) s = fmaf(hid[i], w2[i * 12 + tid], s);
        g_btab[e * 12 + tid] = 16.f / (1.f + expf(-s));
    }
}

__global__ void bias_expand_kernel(const int* __restrict__ rpi,
                                   const float* __restrict__ mask) {
    int idx = blockIdx.x * 256 + threadIdx.x;
    if (idx >= 16 * 12 * 144 * 144) return;
    int rj = idx % (144 * 144);
    int wh = idx / (144 * 144);
    int h = wh % 12, wt = wh / 12;
    g_bias2[idx] = g_btab[rpi[rj] * 12 + h] + mask[wt * 144 * 144 + rj];
}

// ---------------------------------------------------------------------------
// fp16 GEMM: 128x128 tile, BK=32, 4-stage cp.async pipeline, 256 threads,
// 8 warps each 32x64 via mma.m16n8k16; fragment loads via ldmatrix.x4.
// Stage index == commit-group index (unconditional commit per iteration).
// MODE 0: qkv (A gathered; scatter epilogue, f32 out + q/v bias)
// MODE 1: bias, f32 out
// MODE 2: bias + exact GELU, fp16 out
// ---------------------------------------------------------------------------
template <int MODE, int Ncols, int Kdim>
__global__ void __launch_bounds__(256, 2) gemm_h1(
    const __half* __restrict__ A_g, const __half* __restrict__ B_g,
    const float* __restrict__ bias, const float* __restrict__ bias2,
    float* __restrict__ CoutF, __half* __restrict__ CoutH) {
    extern __shared__ uint32_t smw[];
    uint32_t sb = smem_u32(smw);

    int tid = threadIdx.x;
    int bx = blockIdx.x, by = blockIdx.y;
    int warp = tid >> 5, lane = tid & 31;
    int g = lane >> 2, t = lane & 3;
    int wm = (warp & 3) * 32, wn = (warp >> 2) * 64;
    constexpr int NCHUNK = Kdim / 32;

    // ldmatrix per-thread tile-row offsets (bytes within stage):
    uint32_t a_off = (uint32_t)((wm + (lane & 15)) * ST2 * 4 + (lane >> 4) * 16);
    uint32_t b_off = (uint32_t)(BUFW * 4 +
        (wn + (lane & 7) + ((lane >> 4) << 3)) * ST2 * 4 + ((lane >> 3) & 1) * 16);

    // load map: each thread copies 2 chunks of A and 2 of B (16B each).
    int lrow = tid >> 1;
    int segb = (tid & 1) * 2;
    long arow;
    {
        int gr = by * 128 + lrow;
        arow = (MODE == 0) ? (long)win_src_row(gr) : (long)gr;
    }
    long brow = bx * 128 + lrow;

    auto load_stage = [&](int s, int kc) {
        uint32_t stb = sb + s * (STAGEW * 4);
        uint32_t da = stb + lrow * (ST2 * 4) + segb * 16;
        uint32_t db = da + BUFW * 4;
        const __half* ga = A_g + arow * Kdim + kc + segb * 8;
        const __half* gb = B_g + brow * Kdim + kc + segb * 8;
        cpa16(da,      ga);
        cpa16(da + 16, ga + 8);
        cpa16(db,      gb);
        cpa16(db + 16, gb + 8);
    };

    float acc[2][8][4];
    #pragma unroll
    for (int i = 0; i < 2; i++)
        #pragma unroll
        for (int j = 0; j < 8; j++)
            #pragma unroll
            for (int q = 0; q < 4; q++) acc[i][j][q] = 0.f;

    // preload stages 0..2
    #pragma unroll
    for (int i = 0; i < 3; i++) {
        if (i < NCHUNK) load_stage(i, i * 32);
        cpa_commit();
    }

    for (int c = 0; c < NCHUNK; c++) {
        cpa_wait<2>();            // guarantees group/stage c complete
        __syncthreads();
        uint32_t stb = sb + (c & (NSTAGE - 1)) * (STAGEW * 4);
        #pragma unroll
        for (int kk = 0; kk < 2; kk++) {      // two k16 steps
            uint32_t kb = kk * 32;
            uint32_t ah[2][4];
            ldsm_x4(ah[0], stb + a_off + kb);
            ldsm_x4(ah[1], stb + a_off + 16 * ST2 * 4 + kb);
            uint32_t bf[4][4];
            #pragma unroll
            for (int ntp = 0; ntp < 4; ntp++)
                ldsm_x4(bf[ntp], stb + b_off + ntp * 16 * ST2 * 4 + kb);
            #pragma unroll
            for (int ntp = 0; ntp < 4; ntp++) {
                #pragma unroll
                for (int mt = 0; mt < 2; mt++) {
                    mma16(acc[mt][2 * ntp + 0], ah[mt], &bf[ntp][0]);
                    mma16(acc[mt][2 * ntp + 1], ah[mt], &bf[ntp][2]);
                }
            }
        }
        if (c + 3 < NCHUNK) load_stage((c + 3) & (NSTAGE - 1), (c + 3) * 32);
        cpa_commit();             // unconditional: keeps group==stage mapping
    }

    // ---- epilogue ----
    int gr = by * 128 + wm + g;
    int gc = bx * 128 + wn + 2 * t;
    #pragma unroll
    for (int mt = 0; mt < 2; mt++) {
        int r0 = gr + mt * 16;
        #pragma unroll
        for (int nt = 0; nt < 8; nt++) {
            int c0 = gc + nt * 8;
            if (MODE == 0) {
                #pragma unroll
                for (int e = 0; e < 4; e++) {
                    int row = r0 + (e >> 1) * 8;
                    int col = c0 + (e & 1);
                    int wi = row / kN, tk = row - wi * kN;
                    int part = col / kC, cc = col - part * kC;
                    float bv = (part == 0) ? bias[cc] : (part == 2 ? bias2[cc] : 0.f);
                    g_scratch[(long)part * kSLOT +
                              (((long)(wi * kNH + (cc >> 5))) * kN + tk) * kHD + (cc & 31)]
                        = acc[mt][nt][e] + bv;
                }
            } else if (MODE == 1) {
                float b0 = bias[c0], b1 = bias[c0 + 1];
                float2 v;
                v.x = acc[mt][nt][0] + b0; v.y = acc[mt][nt][1] + b1;
                *(float2*)&CoutF[(long)r0 * Ncols + c0] = v;
                v.x = acc[mt][nt][2] + b0; v.y = acc[mt][nt][3] + b1;
                *(float2*)&CoutF[(long)(r0 + 8) * Ncols + c0] = v;
            } else {
                float b0 = bias[c0], b1 = bias[c0 + 1];
                #pragma unroll
                for (int hh = 0; hh < 2; hh++) {
                    float vx = acc[mt][nt][2 * hh + 0] + b0;
                    float vy = acc[mt][nt][2 * hh + 1] + b1;
                    vx = 0.5f * vx * (1.f + erff(vx * 0.70710678f));
                    vy = 0.5f * vy * (1.f + erff(vy * 0.70710678f));
                    long off = (long)(r0 + 8 * hh) * Ncols + c0;
                    *(__half2*)(CoutH + off) =
                        __halves2half2(__float2half_rn(vx), __float2half_rn(vy));
                }
            }
        }
    }
}

// ---------------------------------------------------------------------------
// K3: cosine attention, one block per (window, head). 160 threads, 1 row each.
// Fixed stabilizer mx = scale + 16.  Output: fp16 (proj operand).
// ---------------------------------------------------------------------------
__global__ void __launch_bounds__(160) attn_kernel(const float* __restrict__ lsc,
                                                   __half* __restrict__ Oh) {
    __shared__ float4 ks4[144 * 8];
    __shared__ float4 vs4[144 * 8];
    int bh = blockIdx.x;
    int wi = bh / kNH, h = bh - wi * kNH;
    int tid = threadIdx.x;

    const float4* qg = (const float4*)(g_scratch + 0 * kSLOT + (long)bh * kN * kHD);
    const float4* kg = (const float4*)(g_scratch + 1 * kSLOT + (long)bh * kN * kHD);
    const float4* vg = (const float4*)(g_scratch + 2 * kSLOT + (long)bh * kN * kHD);

    for (int i = tid; i < 144 * 8; i += 160) {
        ks4[i] = kg[i];
        vs4[i] = vg[i];
    }
    __syncthreads();
    if (tid < kN) {
        float s = 0.f;
        float4 kr[8];
        #pragma unroll
        for (int d = 0; d < 8; d++) {
            kr[d] = ks4[tid * 8 + d];
            s += kr[d].x * kr[d].x + kr[d].y * kr[d].y + kr[d].z * kr[d].z + kr[d].w * kr[d].w;
        }
        float inv = 1.f / fmaxf(sqrtf(s), 1e-12f);
        #pragma unroll
        for (int d = 0; d < 8; d++) {
            kr[d].x *= inv; kr[d].y *= inv; kr[d].z *= inv; kr[d].w *= inv;
            ks4[tid * 8 + d] = kr[d];
        }
    }
    __syncthreads();

    if (tid < kN) {
        int r = tid;
        float scale = __expf(fminf(lsc[h], 4.605170185988092f));
        float4 qr[8];
        float s = 0.f;
        #pragma unroll
        for (int d = 0; d < 8; d++) {
            qr[d] = qg[r * 8 + d];
            s += qr[d].x * qr[d].x + qr[d].y * qr[d].y + qr[d].z * qr[d].z + qr[d].w * qr[d].w;
        }
        float inv = scale / fmaxf(sqrtf(s), 1e-12f);
        #pragma unroll
        for (int d = 0; d < 8; d++) {
            qr[d].x *= inv; qr[d].y *= inv; qr[d].z *= inv; qr[d].w *= inv;
        }

        const float* comb = g_bias2 + ((long)((wi & 15) * kNH + h) * kN + r) * kN;
        float mx = scale + 16.f;
        float4 o[8];
        #pragma unroll
        for (int d = 0; d < 8; d++) o[d] = make_float4(0.f, 0.f, 0.f, 0.f);
        float sum = 0.f;
        for (int j = 0; j < kN; j++) {
            float tt = comb[j];
            #pragma unroll
            for (int d = 0; d < 8; d++) {
                float4 kv = ks4[j * 8 + d];
                tt = fmaf(qr[d].x, kv.x, tt);
                tt = fmaf(qr[d].y, kv.y, tt);
                tt = fmaf(qr[d].z, kv.z, tt);
                tt = fmaf(qr[d].w, kv.w, tt);
            }
            float e = __expf(tt - mx);
            sum += e;
            #pragma unroll
            for (int d = 0; d < 8; d++) {
                float4 vv = vs4[j * 8 + d];
                o[d].x = fmaf(e, vv.x, o[d].x);
                o[d].y = fmaf(e, vv.y, o[d].y);
                o[d].z = fmaf(e, vv.z, o[d].z);
                o[d].w = fmaf(e, vv.w, o[d].w);
            }
        }
        float rs = 1.f / sum;
        long obase = (long)(wi * kN + r) * kC + h * kHD;
        #pragma unroll
        for (int d = 0; d < 8; d++) {
            *(__half2*)(Oh + obase + 4 * d) =
                __halves2half2(__float2half_rn(o[d].x * rs), __float2half_rn(o[d].y * rs));
            *(__half2*)(Oh + obase + 4 * d + 2) =
                __halves2half2(__float2half_rn(o[d].z * rs), __float2half_rn(o[d].w * rs));
        }
    }
}

// ---------------------------------------------------------------------------
// LN + residual. SCATTER: window->image reorder + emit fp16 copy.
// ---------------------------------------------------------------------------
template <bool SCATTER>
__global__ void __launch_bounds__(128) ln_res_kernel(
    const float* __restrict__ src, const float* __restrict__ resid,
    const float* __restrict__ gam, const float* __restrict__ bet,
    float* __restrict__ out, __half* __restrict__ Sh) {
    int m = blockIdx.x;
    int dst = SCATTER ? win_src_row(m) : m;
    const float* row = src + (long)m * kC;
    int tid = threadIdx.x;
    float v0 = row[tid], v1 = row[tid + 128], v2 = row[tid + 256];
    float s = v0 + v1 + v2;
    float s2 = v0 * v0 + v1 * v1 + v2 * v2;
    #pragma unroll
    for (int o = 16; o > 0; o >>= 1) {
        s  += __shfl_xor_sync(0xffffffffu, s, o);
        s2 += __shfl_xor_sync(0xffffffffu, s2, o);
    }
    __shared__ float sh[8];
    int wid = tid >> 5, lane = tid & 31;
    if (lane == 0) { sh[wid] = s; sh[4 + wid] = s2; }
    __syncthreads();
    s  = sh[0] + sh[1] + sh[2] + sh[3];
    s2 = sh[4] + sh[5] + sh[6] + sh[7];
    float mean = s * (1.f / 384.f);
    float var = s2 * (1.f / 384.f) - mean * mean;
    float rstd = rsqrtf(var + 1e-5f);
    const float* rrow = resid + (long)dst * kC;
    float* orow = out + (long)dst * kC;
    #pragma unroll
    for (int q = 0; q < 3; q++) {
        int col = tid + 128 * q;
        float v = (q == 0 ? v0 : (q == 1 ? v1 : v2));
        float y = rrow[col] + (v - mean) * rstd * gam[col] + bet[col];
        orow[col] = y;
        if (SCATTER) Sh[(long)dst * kC + col] = __float2half_rn(y);
    }
}

// ---------------------------------------------------------------------------
extern "C" void kernel_launch(void* const* d_in, const int* in_sizes, int n_in,
                              void* d_out, int out_size) {
    const float* x    = (const float*)d_in[0];
    const float* tab  = (const float*)d_in[1];
    const int*   rpi  = (const int*)  d_in[2];
    const float* mask = (const float*)d_in[3];
    const float* qkvw = (const float*)d_in[4];
    const float* qb   = (const float*)d_in[5];
    const float* vb   = (const float*)d_in[6];
    const float* lsc  = (const float*)d_in[7];
    const float* w1   = (const float*)d_in[8];
    const float* b1   = (const float*)d_in[9];
    const float* w2   = (const float*)d_in[10];
    const float* pw   = (const float*)d_in[11];
    const float* pb   = (const float*)d_in[12];
    const float* n1g  = (const float*)d_in[13];
    const float* n1b  = (const float*)d_in[14];
    const float* n2g  = (const float*)d_in[15];
    const float* n2b  = (const float*)d_in[16];
    const float* f1w  = (const float*)d_in[17];
    const float* f1b  = (const float*)d_in[18];
    const float* f2w  = (const float*)d_in[19];
    const float* f2b  = (const float*)d_in[20];
    float* out = (float*)d_out;

    float* f = nullptr;
    cudaGetSymbolAddress((void**)&f, g_scratch);
    __half* whi = nullptr; cudaGetSymbolAddress((void**)&whi, g_whi);

    // scratch map
    __half* attn_h = (__half*)(f + 3 * kSLOT);
    __half* x_h    = (__half*)(f + 4 * kSLOT);   // reused as x1_h
    float*  proj_f = f + 5 * kSLOT;
    float*  x1_f   = f + 1 * kSLOT;
    __half* h_h    = (__half*)(f + 2 * kSLOT);   // kM x 1536 halves, spans s2,s3
    float*  y_f    = f + 7 * kSLOT;

    cudaFuncSetAttribute(gemm_h1<0, 1152, 384>, cudaFuncAttributeMaxDynamicSharedMemorySize, SMEM_DYN);
    cudaFuncSetAttribute(gemm_h1<1, 384, 384>,  cudaFuncAttributeMaxDynamicSharedMemorySize, SMEM_DYN);
    cudaFuncSetAttribute(gemm_h1<2, 1536, 384>, cudaFuncAttributeMaxDynamicSharedMemorySize, SMEM_DYN);
    cudaFuncSetAttribute(gemm_h1<1, 384, 1536>, cudaFuncAttributeMaxDynamicSharedMemorySize, SMEM_DYN);

    // 0. weight transposes (fp16 [n][k]) + x convert
    wsplit_kernel<<<(442368 + 255) / 256, 256>>>(qkvw, whi + OQKV, 384, 1152);
    wsplit_kernel<<<(147456 + 255) / 256, 256>>>(pw,  whi + OPROJ, 384, 384);
    wsplit_kernel<<<(589824 + 255) / 256, 256>>>(f1w, whi + OFC1,  384, 1536);
    wsplit_kernel<<<(589824 + 255) / 256, 256>>>(f2w, whi + OFC2,  1536, 384);
    xsplit_kernel<<<(int)((kSLOT + 255) / 256), 256>>>(x, x_h, kSLOT);

    // 1. CPB bias table + expansion (bias + mask combined)
    cpb_kernel<<<529, 512>>>(tab, w1, b1, w2);
    bias_expand_kernel<<<(16 * 12 * 144 * 144 + 255) / 256, 256>>>(rpi, mask);

    // 2. QKV GEMM (gathered A) -> q/k/v f32 slots
    gemm_h1<0, 1152, 384><<<dim3(9, 576), 256, SMEM_DYN>>>(
        x_h, whi + OQKV, qb, vb, nullptr, nullptr);

    // 3. attention -> attn_h
    attn_kernel<<<512 * kNH, 160>>>(lsc, attn_h);

    // 4. proj GEMM -> proj_f
    gemm_h1<1, 384, 384><<<dim3(3, 576), 256, SMEM_DYN>>>(
        attn_h, whi + OPROJ, pb, nullptr, proj_f, nullptr);

    // 5. LN1 + residual + scatter -> x1_f + x1_h
    ln_res_kernel<true><<<kM, 128>>>(proj_f, x, n1g, n1b, x1_f, x_h);

    // 6. fc1 + GELU -> h_h
    gemm_h1<2, 1536, 384><<<dim3(12, 576), 256, SMEM_DYN>>>(
        x_h, whi + OFC1, f1b, nullptr, nullptr, h_h);

    // 7. fc2 -> y_f
    gemm_h1<1, 384, 1536><<<dim3(3, 576), 256, SMEM_DYN>>>(
        h_h, whi + OFC2, f2b, nullptr, y_f, nullptr);

    // 8. final LN + residual -> out
    ln_res_kernel<false><<<kM, 128>>>(y_f, x1_f, n2g, n2b, out, nullptr);
}

// round 15
// speedup vs baseline: 1.3496x; 1.3496x over previous
#include <cuda_runtime.h>
#include <cuda_fp16.h>
#include <math.h>
#include <stdint.h>

// ---------------------------------------------------------------------------
// SwinV2 block: B=32, H=W=48, C=384, NH=12, WS=12, N=144, SHIFT=6
// GEMMs: fp16 mma.m16n8k16, 2-stage cp.async, ldmatrix (Round-8 config).
// Attention: tensor-core, 3-term hi/lo S + fp16 PV (P scaled by 2^15 to
// escape fp16 subnormal range under the fixed softmax stabilizer).
// ---------------------------------------------------------------------------
namespace {
constexpr int kH = 48;
constexpr int kW = 48;
constexpr int kC = 384;
constexpr int kNH = 12;
constexpr int kHD = 32;
constexpr int kWS = 12;
constexpr int kN = 144;
constexpr int kSHIFT = 6;
constexpr int kM = 73728;        // 512 windows * 144 tokens
constexpr long kSLOT = 28311552; // kM * kC elements

constexpr int ST2 = 20;          // smem row stride in 32-bit words (40 halves)
constexpr int BUFW = 128 * ST2;  // words per operand buffer (2560)
constexpr int STAGEW = 2 * BUFW; // A | B per stage (5120 words)
constexpr int SMEM_DYN = 2 * STAGEW * 4;  // 40960 B

// attention smem layout (halves)
constexpr int AQH = 0;              // 144 x 40
constexpr int AQL = 5760;
constexpr int AKH = 11520;
constexpr int AKL = 17280;
constexpr int AVT = 23040;          // 32 x 152  (vt[dim][tok])
constexpr int VST = 152;
constexpr int SMEM_ATTN = (23040 + 32 * 152) * 2;  // 55808 B

constexpr float kPScale = 32768.f;  // 2^15: lifts P out of fp16 subnormals

// fp16 weight offsets (halves), [n][k] layout
constexpr long OQKV = 0;        // 1152 x 384
constexpr long OPROJ = 442368;  // 384 x 384
constexpr long OFC1 = 589824;   // 1536 x 384
constexpr long OFC2 = 1179648;  // 384 x 1536
}

// scratch slots (28311552 f32 each):
// s0 q | s1 k -> x1 f32 | s2 v -> h_h(spans s2,s3) | s3 attn_h
// s4 x_h -> x1_h | s5 proj_f | s7 y_f
__device__ float g_scratch[8 * 28311552ULL];
__device__ float g_btab[529 * 12];
__device__ float g_bias2[16 * 12 * 144 * 144];
__device__ __align__(16) __half g_whi[1769472];

__device__ __forceinline__ int win_src_row(int m) {
    int wi = m / kN, t = m - wi * kN;
    int b  = wi >> 4;
    int wh = (wi >> 2) & 3;
    int ww = wi & 3;
    int th = t / kWS, tw = t - th * kWS;
    int sh = wh * kWS + th + kSHIFT; if (sh >= kH) sh -= kH;
    int sw = ww * kWS + tw + kSHIFT; if (sw >= kW) sw -= kW;
    return (b * kH + sh) * kW + sw;
}

__device__ __forceinline__ uint32_t smem_u32(const void* p) {
    uint32_t a;
    asm("{ .reg .u64 t; cvta.to.shared.u64 t, %1; cvt.u32.u64 %0, t; }" : "=r"(a) : "l"(p));
    return a;
}
__device__ __forceinline__ void mma16(float* c, const uint32_t* a, const uint32_t* b) {
    asm volatile("mma.sync.aligned.m16n8k16.row.col.f32.f16.f16.f32 "
        "{%0,%1,%2,%3},{%4,%5,%6,%7},{%8,%9},{%0,%1,%2,%3};"
        : "+f"(c[0]), "+f"(c[1]), "+f"(c[2]), "+f"(c[3])
        : "r"(a[0]), "r"(a[1]), "r"(a[2]), "r"(a[3]), "r"(b[0]), "r"(b[1]));
}
__device__ __forceinline__ void ldsm_x4(uint32_t* r, uint32_t addr) {
    asm volatile("ldmatrix.sync.aligned.m8n8.x4.shared.b16 {%0,%1,%2,%3}, [%4];"
        : "=r"(r[0]), "=r"(r[1]), "=r"(r[2]), "=r"(r[3]) : "r"(addr));
}
__device__ __forceinline__ void cpa16(uint32_t dst, const void* src) {
    asm volatile("cp.async.ca.shared.global [%0], [%1], 16;" :: "r"(dst), "l"(src));
}
__device__ __forceinline__ void cpa_commit() {
    asm volatile("cp.async.commit_group;" ::: "memory");
}
template <int Nw>
__device__ __forceinline__ void cpa_wait() {
    asm volatile("cp.async.wait_group %0;" :: "n"(Nw) : "memory");
}
__device__ __forceinline__ uint32_t pack2(float a, float b) {
    __half2 h = __floats2half2_rn(a, b);
    return *(uint32_t*)&h;
}

// ---------------------------------------------------------------------------
// K0a: weight transpose to fp16.  W[K][N] -> hi[n][k]
// ---------------------------------------------------------------------------
__global__ void wsplit_kernel(const float* __restrict__ W,
                              __half* __restrict__ hi, int K, int N) {
    long idx = (long)blockIdx.x * 256 + threadIdx.x;
    if (idx >= (long)K * N) return;
    int n = (int)(idx / K), k = (int)(idx % K);
    hi[idx] = __float2half_rn(W[(long)k * N + n]);
}

// K0b: activation convert
__global__ void xsplit_kernel(const float* __restrict__ X,
                              __half* __restrict__ hi, long n) {
    long i = (long)blockIdx.x * 256 + threadIdx.x;
    if (i < n) hi[i] = __float2half_rn(X[i]);
}

// ---------------------------------------------------------------------------
// K1: CPB MLP -> 16*sigmoid table; K1b: expand + fold mask
// ---------------------------------------------------------------------------
__global__ void cpb_kernel(const float* __restrict__ table,
                           const float* __restrict__ w1,
                           const float* __restrict__ b1,
                           const float* __restrict__ w2) {
    __shared__ float hid[512];
    int e = blockIdx.x;
    int tid = threadIdx.x;
    float t0 = table[e * 2 + 0], t1 = table[e * 2 + 1];
    hid[tid] = fmaxf(0.f, fmaf(t0, w1[tid], fmaf(t1, w1[512 + tid], b1[tid])));
    __syncthreads();
    if (tid < 12) {
        float s = 0.f;
        #pragma unroll 8
        for (int i = 0; i < 512; i++) s = fmaf(hid[i], w2[i * 12 + tid], s);
        g_btab[e * 12 + tid] = 16.f / (1.f + expf(-s));
    }
}

__global__ void bias_expand_kernel(const int* __restrict__ rpi,
                                   const float* __restrict__ mask) {
    int idx = blockIdx.x * 256 + threadIdx.x;
    if (idx >= 16 * 12 * 144 * 144) return;
    int rj = idx % (144 * 144);
    int wh = idx / (144 * 144);
    int h = wh % 12, wt = wh / 12;
    g_bias2[idx] = g_btab[rpi[rj] * 12 + h] + mask[wt * 144 * 144 + rj];
}

// ---------------------------------------------------------------------------
// fp16 GEMM: 128x128 tile, BK=32, 2-stage cp.async, 256 threads,
// 8 warps each 32x64 via mma.m16n8k16; fragment loads via ldmatrix.x4.
// MODE 0: qkv (A gathered; scatter epilogue, f32 out + q/v bias)
// MODE 1: bias, f32 out
// MODE 2: bias + exact GELU, fp16 out
// ---------------------------------------------------------------------------
template <int MODE, int Ncols, int Kdim>
__global__ void __launch_bounds__(256, 2) gemm_h1(
    const __half* __restrict__ A_g, const __half* __restrict__ B_g,
    const float* __restrict__ bias, const float* __restrict__ bias2,
    float* __restrict__ CoutF, __half* __restrict__ CoutH) {
    extern __shared__ uint32_t smw[];
    uint32_t sb = smem_u32(smw);

    int tid = threadIdx.x;
    int bx = blockIdx.x, by = blockIdx.y;
    int warp = tid >> 5, lane = tid & 31;
    int g = lane >> 2, t = lane & 3;
    int wm = (warp & 3) * 32, wn = (warp >> 2) * 64;
    constexpr int NCHUNK = Kdim / 32;

    uint32_t a_off = (uint32_t)((wm + (lane & 15)) * ST2 * 4 + (lane >> 4) * 16);
    uint32_t b_off = (uint32_t)(BUFW * 4 +
        (wn + (lane & 7) + ((lane >> 4) << 3)) * ST2 * 4 + ((lane >> 3) & 1) * 16);

    int lrow = tid >> 1;
    int segb = (tid & 1) * 2;
    long arow;
    {
        int gr = by * 128 + lrow;
        arow = (MODE == 0) ? (long)win_src_row(gr) : (long)gr;
    }
    long brow = bx * 128 + lrow;

    auto load_stage = [&](int s, int kc) {
        uint32_t stb = sb + s * (STAGEW * 4);
        uint32_t da = stb + lrow * (ST2 * 4) + segb * 16;
        uint32_t db = da + BUFW * 4;
        const __half* ga = A_g + arow * Kdim + kc + segb * 8;
        const __half* gb = B_g + brow * Kdim + kc + segb * 8;
        cpa16(da,      ga);
        cpa16(da + 16, ga + 8);
        cpa16(db,      gb);
        cpa16(db + 16, gb + 8);
    };

    float acc[2][8][4];
    #pragma unroll
    for (int i = 0; i < 2; i++)
        #pragma unroll
        for (int j = 0; j < 8; j++)
            #pragma unroll
            for (int q = 0; q < 4; q++) acc[i][j][q] = 0.f;

    load_stage(0, 0);
    cpa_commit();

    for (int c = 0; c < NCHUNK; c++) {
        if (c + 1 < NCHUNK) load_stage((c + 1) & 1, (c + 1) * 32);
        cpa_commit();
        cpa_wait<1>();
        __syncthreads();
        uint32_t stb = sb + (c & 1) * (STAGEW * 4);
        #pragma unroll
        for (int kk = 0; kk < 2; kk++) {
            uint32_t kb = kk * 32;
            uint32_t ah[2][4];
            ldsm_x4(ah[0], stb + a_off + kb);
            ldsm_x4(ah[1], stb + a_off + 16 * ST2 * 4 + kb);
            uint32_t bf[4][4];
            #pragma unroll
            for (int ntp = 0; ntp < 4; ntp++)
                ldsm_x4(bf[ntp], stb + b_off + ntp * 16 * ST2 * 4 + kb);
            #pragma unroll
            for (int ntp = 0; ntp < 4; ntp++) {
                #pragma unroll
                for (int mt = 0; mt < 2; mt++) {
                    mma16(acc[mt][2 * ntp + 0], ah[mt], &bf[ntp][0]);
                    mma16(acc[mt][2 * ntp + 1], ah[mt], &bf[ntp][2]);
                }
            }
        }
        __syncthreads();
    }

    // ---- epilogue ----
    int gr = by * 128 + wm + g;
    int gc = bx * 128 + wn + 2 * t;
    #pragma unroll
    for (int mt = 0; mt < 2; mt++) {
        int r0 = gr + mt * 16;
        #pragma unroll
        for (int nt = 0; nt < 8; nt++) {
            int c0 = gc + nt * 8;
            if (MODE == 0) {
                #pragma unroll
                for (int e = 0; e < 4; e++) {
                    int row = r0 + (e >> 1) * 8;
                    int col = c0 + (e & 1);
                    int wi = row / kN, tk = row - wi * kN;
                    int part = col / kC, cc = col - part * kC;
                    float bv = (part == 0) ? bias[cc] : (part == 2 ? bias2[cc] : 0.f);
                    g_scratch[(long)part * kSLOT +
                              (((long)(wi * kNH + (cc >> 5))) * kN + tk) * kHD + (cc & 31)]
                        = acc[mt][nt][e] + bv;
                }
            } else if (MODE == 1) {
                float b0 = bias[c0], b1 = bias[c0 + 1];
                float2 v;
                v.x = acc[mt][nt][0] + b0; v.y = acc[mt][nt][1] + b1;
                *(float2*)&CoutF[(long)r0 * Ncols + c0] = v;
                v.x = acc[mt][nt][2] + b0; v.y = acc[mt][nt][3] + b1;
                *(float2*)&CoutF[(long)(r0 + 8) * Ncols + c0] = v;
            } else {
                float b0 = bias[c0], b1 = bias[c0 + 1];
                #pragma unroll
                for (int hh = 0; hh < 2; hh++) {
                    float vx = acc[mt][nt][2 * hh + 0] + b0;
                    float vy = acc[mt][nt][2 * hh + 1] + b1;
                    vx = 0.5f * vx * (1.f + erff(vx * 0.70710678f));
                    vy = 0.5f * vy * (1.f + erff(vy * 0.70710678f));
                    long off = (long)(r0 + 8 * hh) * Ncols + c0;
                    *(__half2*)(CoutH + off) =
                        __halves2half2(__float2half_rn(vx), __float2half_rn(vy));
                }
            }
        }
    }
}

// ---------------------------------------------------------------------------
// K3: tensor-core cosine attention. One block per (window, head), 128 thr.
// S = QKt via 3-term fp16 hi/lo mma; softmax with fixed stabilizer
// mx = scale+16; P scaled by 2^15 before fp16 packing; PV via fp16 mma.
// ---------------------------------------------------------------------------
__global__ void __launch_bounds__(128) attn_mma_kernel(
    const float* __restrict__ lsc, __half* __restrict__ Oh) {
    extern __shared__ __half sm[];
    int bh = blockIdx.x;
    int wi = bh / kNH, h = bh - wi * kNH;
    int tid = threadIdx.x;
    int warp = tid >> 5, lane = tid & 31;
    int g = lane >> 2, t = lane & 3;

    const float* qg = g_scratch + 0 * kSLOT + (long)bh * kN * kHD;
    const float* kg = g_scratch + 1 * kSLOT + (long)bh * kN * kHD;
    const float* vg = g_scratch + 2 * kSLOT + (long)bh * kN * kHD;

    float scale = __expf(fminf(lsc[h], 4.605170185988092f)); // log(100)

    // ---- load + normalize + split ----
    for (int r = tid; r < kN; r += 128) {
        float q[32], k[32], v[32];
        #pragma unroll
        for (int i = 0; i < 8; i++) {
            *(float4*)&q[4 * i] = *(const float4*)(qg + r * 32 + 4 * i);
            *(float4*)&k[4 * i] = *(const float4*)(kg + r * 32 + 4 * i);
            *(float4*)&v[4 * i] = *(const float4*)(vg + r * 32 + 4 * i);
        }
        float sq = 0.f, sk = 0.f;
        #pragma unroll
        for (int d = 0; d < 32; d++) { sq = fmaf(q[d], q[d], sq); sk = fmaf(k[d], k[d], sk); }
        float invq = scale / fmaxf(sqrtf(sq), 1e-12f);
        float invk = 1.f / fmaxf(sqrtf(sk), 1e-12f);
        #pragma unroll
        for (int d = 0; d < 32; d++) {
            float qv = q[d] * invq;
            __half qh_ = __float2half_rn(qv);
            sm[AQH + r * 40 + d] = qh_;
            sm[AQL + r * 40 + d] = __float2half_rn(qv - __half2float(qh_));
            float kv = k[d] * invk;
            __half kh_ = __float2half_rn(kv);
            sm[AKH + r * 40 + d] = kh_;
            sm[AKL + r * 40 + d] = __float2half_rn(kv - __half2float(kh_));
            sm[AVT + d * VST + r] = __float2half_rn(v[d]);
        }
    }
    __syncthreads();

    uint32_t qh_b = smem_u32(sm + AQH), ql_b = smem_u32(sm + AQL);
    uint32_t kh_b = smem_u32(sm + AKH), kl_b = smem_u32(sm + AKL);
    uint32_t vt_b = smem_u32(sm + AVT);

    const float* biasbase = g_bias2 + ((long)((wi & 15) * kNH + h)) * kN * kN;
    float mx = scale + 16.f;

    for (int mt = warp; mt < 9; mt += 4) {
        int m0 = mt * 16;
        uint32_t aoff = (uint32_t)(((m0 + (lane & 15)) * 40 + (lane >> 4) * 8) * 2);
        uint32_t aqh[2][4], aql[2][4];
        ldsm_x4(aqh[0], qh_b + aoff);
        ldsm_x4(aqh[1], qh_b + aoff + 32);
        ldsm_x4(aql[0], ql_b + aoff);
        ldsm_x4(aql[1], ql_b + aoff + 32);

        uint32_t ap[9][4];
        float rsum0 = 0.f, rsum1 = 0.f;
        #pragma unroll
        for (int np = 0; np < 9; np++) {
            int n0 = np * 16;
            uint32_t boff = (uint32_t)(((n0 + (lane & 7) + ((lane >> 4) << 3)) * 40 +
                                        ((lane >> 3) & 1) * 8) * 2);
            uint32_t bh0[4], bh1[4], bl0[4], bl1[4];
            ldsm_x4(bh0, kh_b + boff);
            ldsm_x4(bh1, kh_b + boff + 32);
            ldsm_x4(bl0, kl_b + boff);
            ldsm_x4(bl1, kl_b + boff + 32);
            float c0[4] = {0.f, 0.f, 0.f, 0.f};
            float c1[4] = {0.f, 0.f, 0.f, 0.f};
            // 3-term: hi*hi + hi*lo + lo*hi, over 2 k16 chunks
            mma16(c0, aqh[0], &bh0[0]); mma16(c0, aqh[1], &bh1[0]);
            mma16(c0, aqh[0], &bl0[0]); mma16(c0, aqh[1], &bl1[0]);
            mma16(c0, aql[0], &bh0[0]); mma16(c0, aql[1], &bh1[0]);
            mma16(c1, aqh[0], &bh0[2]); mma16(c1, aqh[1], &bh1[2]);
            mma16(c1, aqh[0], &bl0[2]); mma16(c1, aqh[1], &bl1[2]);
            mma16(c1, aql[0], &bh0[2]); mma16(c1, aql[1], &bh1[2]);

            const float* bp = biasbase + (long)(m0 + g) * kN + n0;
            float2 b00 = *(const float2*)(bp + 2 * t);
            float2 b01 = *(const float2*)(bp + 8 + 2 * t);
            float2 b10 = *(const float2*)(bp + 8 * kN + 2 * t);
            float2 b11 = *(const float2*)(bp + 8 * kN + 8 + 2 * t);
            float e00 = __expf(c0[0] + b00.x - mx);
            float e01 = __expf(c0[1] + b00.y - mx);
            float e02 = __expf(c0[2] + b10.x - mx);
            float e03 = __expf(c0[3] + b10.y - mx);
            float e10 = __expf(c1[0] + b01.x - mx);
            float e11 = __expf(c1[1] + b01.y - mx);
            float e12 = __expf(c1[2] + b11.x - mx);
            float e13 = __expf(c1[3] + b11.y - mx);
            rsum0 += e00 + e01 + e10 + e11;
            rsum1 += e02 + e03 + e12 + e13;
            ap[np][0] = pack2(e00 * kPScale, e01 * kPScale);   // row g,   k-lo
            ap[np][1] = pack2(e02 * kPScale, e03 * kPScale);   // row g+8, k-lo
            ap[np][2] = pack2(e10 * kPScale, e11 * kPScale);   // row g,   k-hi
            ap[np][3] = pack2(e12 * kPScale, e13 * kPScale);   // row g+8, k-hi
        }
        rsum0 += __shfl_xor_sync(0xffffffffu, rsum0, 1);
        rsum0 += __shfl_xor_sync(0xffffffffu, rsum0, 2);
        rsum1 += __shfl_xor_sync(0xffffffffu, rsum1, 1);
        rsum1 += __shfl_xor_sync(0xffffffffu, rsum1, 2);
        float rs0 = 1.f / (rsum0 * kPScale);
        float rs1 = 1.f / (rsum1 * kPScale);

        // ---- PV ----
        float o[4][4];
        #pragma unroll
        for (int i = 0; i < 4; i++)
            #pragma unroll
            for (int q = 0; q < 4; q++) o[i][q] = 0.f;
        #pragma unroll
        for (int np = 0; np < 9; np++) {
            uint32_t voff = (uint32_t)((((lane & 7) + ((lane >> 4) << 3)) * VST +
                                        np * 16 + ((lane >> 3) & 1) * 8) * 2);
            uint32_t bv0[4], bv1[4];
            ldsm_x4(bv0, vt_b + voff);
            ldsm_x4(bv1, vt_b + voff + 16 * VST * 2);
            mma16(o[0], ap[np], &bv0[0]);
            mma16(o[1], ap[np], &bv0[2]);
            mma16(o[2], ap[np], &bv1[0]);
            mma16(o[3], ap[np], &bv1[2]);
        }
        long rowbase = (long)(wi * kN + m0 + g) * kC + h * kHD;
        #pragma unroll
        for (int nt = 0; nt < 4; nt++) {
            int nc = nt * 8 + 2 * t;
            *(__half2*)(Oh + rowbase + nc) =
                __floats2half2_rn(o[nt][0] * rs0, o[nt][1] * rs0);
            *(__half2*)(Oh + rowbase + 8 * kC + nc) =
                __floats2half2_rn(o[nt][2] * rs1, o[nt][3] * rs1);
        }
    }
}

// ---------------------------------------------------------------------------
// LN + residual. SCATTER: window->image reorder + emit fp16 copy.
// ---------------------------------------------------------------------------
template <bool SCATTER>
__global__ void __launch_bounds__(128) ln_res_kernel(
    const float* __restrict__ src, const float* __restrict__ resid,
    const float* __restrict__ gam, const float* __restrict__ bet,
    float* __restrict__ out, __half* __restrict__ Sh) {
    int m = blockIdx.x;
    int dst = SCATTER ? win_src_row(m) : m;
    const float* row = src + (long)m * kC;
    int tid = threadIdx.x;
    float v0 = row[tid], v1 = row[tid + 128], v2 = row[tid + 256];
    float s = v0 + v1 + v2;
    float s2 = v0 * v0 + v1 * v1 + v2 * v2;
    #pragma unroll
    for (int o = 16; o > 0; o >>= 1) {
        s  += __shfl_xor_sync(0xffffffffu, s, o);
        s2 += __shfl_xor_sync(0xffffffffu, s2, o);
    }
    __shared__ float sh[8];
    int wid = tid >> 5, lane = tid & 31;
    if (lane == 0) { sh[wid] = s; sh[4 + wid] = s2; }
    __syncthreads();
    s  = sh[0] + sh[1] + sh[2] + sh[3];
    s2 = sh[4] + sh[5] + sh[6] + sh[7];
    float mean = s * (1.f / 384.f);
    float var = s2 * (1.f / 384.f) - mean * mean;
    float rstd = rsqrtf(var + 1e-5f);
    const float* rrow = resid + (long)dst * kC;
    float* orow = out + (long)dst * kC;
    #pragma unroll
    for (int q = 0; q < 3; q++) {
        int col = tid + 128 * q;
        float v = (q == 0 ? v0 : (q == 1 ? v1 : v2));
        float y = rrow[col] + (v - mean) * rstd * gam[col] + bet[col];
        orow[col] = y;
        if (SCATTER) Sh[(long)dst * kC + col] = __float2half_rn(y);
    }
}

// ---------------------------------------------------------------------------
extern "C" void kernel_launch(void* const* d_in, const int* in_sizes, int n_in,
                              void* d_out, int out_size) {
    const float* x    = (const float*)d_in[0];
    const float* tab  = (const float*)d_in[1];
    const int*   rpi  = (const int*)  d_in[2];
    const float* mask = (const float*)d_in[3];
    const float* qkvw = (const float*)d_in[4];
    const float* qb   = (const float*)d_in[5];
    const float* vb   = (const float*)d_in[6];
    const float* lsc  = (const float*)d_in[7];
    const float* w1   = (const float*)d_in[8];
    const float* b1   = (const float*)d_in[9];
    const float* w2   = (const float*)d_in[10];
    const float* pw   = (const float*)d_in[11];
    const float* pb   = (const float*)d_in[12];
    const float* n1g  = (const float*)d_in[13];
    const float* n1b  = (const float*)d_in[14];
    const float* n2g  = (const float*)d_in[15];
    const float* n2b  = (const float*)d_in[16];
    const float* f1w  = (const float*)d_in[17];
    const float* f1b  = (const float*)d_in[18];
    const float* f2w  = (const float*)d_in[19];
    const float* f2b  = (const float*)d_in[20];
    float* out = (float*)d_out;

    float* f = nullptr;
    cudaGetSymbolAddress((void**)&f, g_scratch);
    __half* whi = nullptr; cudaGetSymbolAddress((void**)&whi, g_whi);

    // scratch map
    __half* attn_h = (__half*)(f + 3 * kSLOT);
    __half* x_h    = (__half*)(f + 4 * kSLOT);   // reused as x1_h
    float*  proj_f = f + 5 * kSLOT;
    float*  x1_f   = f + 1 * kSLOT;
    __half* h_h    = (__half*)(f + 2 * kSLOT);   // kM x 1536 halves, spans s2,s3
    float*  y_f    = f + 7 * kSLOT;

    cudaFuncSetAttribute(gemm_h1<0, 1152, 384>, cudaFuncAttributeMaxDynamicSharedMemorySize, SMEM_DYN);
    cudaFuncSetAttribute(gemm_h1<1, 384, 384>,  cudaFuncAttributeMaxDynamicSharedMemorySize, SMEM_DYN);
    cudaFuncSetAttribute(gemm_h1<2, 1536, 384>, cudaFuncAttributeMaxDynamicSharedMemorySize, SMEM_DYN);
    cudaFuncSetAttribute(gemm_h1<1, 384, 1536>, cudaFuncAttributeMaxDynamicSharedMemorySize, SMEM_DYN);
    cudaFuncSetAttribute(attn_mma_kernel, cudaFuncAttributeMaxDynamicSharedMemorySize, SMEM_ATTN);

    // 0. weight transposes (fp16 [n][k]) + x convert
    wsplit_kernel<<<(442368 + 255) / 256, 256>>>(qkvw, whi + OQKV, 384, 1152);
    wsplit_kernel<<<(147456 + 255) / 256, 256>>>(pw,  whi + OPROJ, 384, 384);
    wsplit_kernel<<<(589824 + 255) / 256, 256>>>(f1w, whi + OFC1,  384, 1536);
    wsplit_kernel<<<(589824 + 255) / 256, 256>>>(f2w, whi + OFC2,  1536, 384);
    xsplit_kernel<<<(int)((kSLOT + 255) / 256), 256>>>(x, x_h, kSLOT);

    // 1. CPB bias table + expansion (bias + mask combined)
    cpb_kernel<<<529, 512>>>(tab, w1, b1, w2);
    bias_expand_kernel<<<(16 * 12 * 144 * 144 + 255) / 256, 256>>>(rpi, mask);

    // 2. QKV GEMM (gathered A) -> q/k/v f32 slots
    gemm_h1<0, 1152, 384><<<dim3(9, 576), 256, SMEM_DYN>>>(
        x_h, whi + OQKV, qb, vb, nullptr, nullptr);

    // 3. attention (tensor core) -> attn_h
    attn_mma_kernel<<<512 * kNH, 128, SMEM_ATTN>>>(lsc, attn_h);

    // 4. proj GEMM -> proj_f
    gemm_h1<1, 384, 384><<<dim3(3, 576), 256, SMEM_DYN>>>(
        attn_h, whi + OPROJ, pb, nullptr, proj_f, nullptr);

    // 5. LN1 + residual + scatter -> x1_f + x1_h
    ln_res_kernel<true><<<kM, 128>>>(proj_f, x, n1g, n1b, x1_f, x_h);

    // 6. fc1 + GELU -> h_h
    gemm_h1<2, 1536, 384><<<dim3(12, 576), 256, SMEM_DYN>>>(
        x_h, whi + OFC1, f1b, nullptr, nullptr, h_h);

    // 7. fc2 -> y_f
    gemm_h1<1, 384, 1536><<<dim3(3, 576), 256, SMEM_DYN>>>(
        h_h, whi + OFC2, f2b, nullptr, y_f, nullptr);

    // 8. final LN + residual -> out
    ln_res_kernel<false><<<kM, 128>>>(y_f, x1_f, n2g, n2b, out, nullptr);
}